// round 9
// baseline (speedup 1.0000x reference)
#include <cuda_runtime.h>

#define W 15            // attention block length
#define DIM 64          // head dim
#define BLK_PER_CTA 4   // one block per warp
#define NTHREADS 128
#define EPS 1e-6f

typedef unsigned long long ull;

__device__ __forceinline__ ull pack2(float lo, float hi) {
    ull r; asm("mov.b64 %0, {%1,%2};" : "=l"(r) : "f"(lo), "f"(hi)); return r;
}
__device__ __forceinline__ void unpack2(ull v, float& lo, float& hi) {
    asm("mov.b64 {%0,%1}, %2;" : "=f"(lo), "=f"(hi) : "l"(v));
}
__device__ __forceinline__ ull fma2(ull a, ull b, ull c) {
    ull d; asm("fma.rn.f32x2 %0, %1, %2, %3;" : "=l"(d) : "l"(a), "l"(b), "l"(c)); return d;
}
__device__ __forceinline__ ull mul2(ull a, ull b) {
    ull d; asm("mul.rn.f32x2 %0, %1, %2;" : "=l"(d) : "l"(a), "l"(b)); return d;
}
__device__ __forceinline__ float shxor(float v, int m) {
    return __shfl_xor_sync(0xffffffffu, v, m, 32);
}

// angle-step literals (phi = pi/30)
#define CA1 0.9945218953682733f   // cos(phi)
#define SA1 0.1045284632676535f   // sin(phi)
#define CA4 0.9135454576426009f   // cos(4*phi)
#define SA4 0.4067366430758002f   // sin(4*phi)
#define CG2 0.9781476007338057f   // cos(2*phi)
#define SG2 0.2079116908177593f
#define CG3 0.9510565162951535f   // cos(3*phi)
#define SG3 0.3090169943749474f

__global__ void __launch_bounds__(NTHREADS, 6)
robust_attn_kernel(const float* __restrict__ q, const float* __restrict__ k,
                   const float* __restrict__ v, float* __restrict__ out, int G)
{
    // relu'd K,V; each warp owns a private 960-float region (no barrier needed)
    __shared__ float sK[BLK_PER_CTA * W * DIM];
    __shared__ float sV[BLK_PER_CTA * W * DIM];

    const int tid = threadIdx.x;
    const int warp = tid >> 5;
    const int lane = tid & 31;
    const int blk = blockIdx.x * BLK_PER_CTA + warp;
    if (blk >= G) return;                       // safe: no CTA-wide sync anywhere
    const size_t base = (size_t)blk * (W * DIM);

    // ---- per-warp fill of own block: 2 batches of 8 LDG.128, relu at store ----
    {
        const float4* gk = (const float4*)(k + base);
        const float4* gv = (const float4*)(v + base);
        float* wK = &sK[warp * (W * DIM)];
        float* wV = &sV[warp * (W * DIM)];
        #pragma unroll
        for (int b = 0; b < 2; ++b) {
            float4 tk[4], tv[4];
            #pragma unroll
            for (int it = 0; it < 4; ++it) {
                int seg = b * 4 + it;
                int i4 = seg * 32 + lane;        // 0..255, valid < 240
                bool ok = (seg < 7) || (lane < 16);
                if (ok) { tk[it] = gk[i4]; tv[it] = gv[i4]; }
            }
            #pragma unroll
            for (int it = 0; it < 4; ++it) {
                int seg = b * 4 + it;
                int i4 = seg * 32 + lane;
                bool ok = (seg < 7) || (lane < 16);
                if (ok) {
                    float4 a = tk[it];
                    a.x = fmaxf(a.x, 0.f); a.y = fmaxf(a.y, 0.f);
                    a.z = fmaxf(a.z, 0.f); a.w = fmaxf(a.w, 0.f);
                    *(float4*)&wK[i4 * 4] = a;
                    float4 c = tv[it];
                    c.x = fmaxf(c.x, 0.f); c.y = fmaxf(c.y, 0.f);
                    c.z = fmaxf(c.z, 0.f); c.w = fmaxf(c.w, 0.f);
                    *(float4*)&wV[i4 * 4] = c;
                }
            }
        }
    }

    const int g = lane & 3;       // row-group: rows g, g+4, g+8, g+12
    const int d = lane >> 2;      // dim-group: dims [8d, 8d+8)
    const int doff = d * 8;

    // ---- per-lane cos/sin of own row angles ----
    float cg = (g == 0) ? 1.0f : (g == 1) ? CA1 : (g == 2) ? CG2 : CG3;
    float sg = (g == 0) ? 0.0f : (g == 1) ? SA1 : (g == 2) ? SG2 : SG3;
    float ci[4], si[4];
    ci[0] = cg; si[0] = sg;
    #pragma unroll
    for (int t = 1; t < 4; ++t) {
        ci[t] = ci[t-1] * CA4 - si[t-1] * SA4;
        si[t] = si[t-1] * CA4 + ci[t-1] * SA4;
    }

    // ---- load + relu q slices for my 4 rows ----
    ull q2[4][4];
    #pragma unroll
    for (int t = 0; t < 4; ++t) {
        int row = g + 4 * t; if (row > W - 1) row = W - 1;
        const float4* qp = (const float4*)(q + base + row * DIM + doff);
        float4 a = qp[0], b = qp[1];
        q2[t][0] = pack2(fmaxf(a.x, 0.f), fmaxf(a.y, 0.f));
        q2[t][1] = pack2(fmaxf(a.z, 0.f), fmaxf(a.w, 0.f));
        q2[t][2] = pack2(fmaxf(b.x, 0.f), fmaxf(b.y, 0.f));
        q2[t][3] = pack2(fmaxf(b.z, 0.f), fmaxf(b.w, 0.f));
    }

    __syncwarp();

    ull acc[4][4];
    #pragma unroll
    for (int t = 0; t < 4; ++t)
        #pragma unroll
        for (int e = 0; e < 4; ++e) acc[t][e] = 0ULL;
    float dn[4] = {0.f, 0.f, 0.f, 0.f};

    const int sbase = warp * (W * DIM) + doff;

    // ---- fused pass over j: packed relu'd K,V from smem (29-cyc LDS) ----
    float cj = 1.0f, sj = 0.0f;   // cos/sin(j*phi)
    #pragma unroll
    for (int j = 0; j < W; ++j) {
        const ulonglong2* kp = (const ulonglong2*)&sK[sbase + j * DIM];
        ulonglong2 kA = kp[0], kB = kp[1];
        const ulonglong2* vp = (const ulonglong2*)&sV[sbase + j * DIM];
        ulonglong2 vA = vp[0], vB = vp[1];

        #pragma unroll
        for (int t = 0; t < 4; ++t) {
            if (4 * t + 3 >= j) {          // compile-time skip of impossible pairs
                ull a = mul2(q2[t][0], kA.x);
                a = fma2(q2[t][1], kA.y, a);
                a = fma2(q2[t][2], kB.x, a);
                a = fma2(q2[t][3], kB.y, a);
                float pl, ph; unpack2(a, pl, ph);
                float pf = pl + ph;
                pf += shxor(pf, 4);
                pf += shxor(pf, 8);
                pf += shxor(pf, 16);
                float s = pf * (ci[t] * cj + si[t] * sj);
                if (4 * t < j) s = (g >= j - 4 * t) ? s : 0.f;
                dn[t] += s;
                ull s2 = pack2(s, s);
                acc[t][0] = fma2(s2, vA.x, acc[t][0]);
                acc[t][1] = fma2(s2, vA.y, acc[t][1]);
                acc[t][2] = fma2(s2, vB.x, acc[t][2]);
                acc[t][3] = fma2(s2, vB.y, acc[t][3]);
            }
        }
        float cjn = cj * CA1 - sj * SA1;
        sj = sj * CA1 + cj * SA1;
        cj = cjn;
    }

    // ---- normalize + store ----
    #pragma unroll
    for (int t = 0; t < 4; ++t) {
        int row = g + 4 * t;
        if (row < W) {
            float rdt = __fdividef(1.0f, fmaxf(dn[t], EPS));
            ull r2 = pack2(rdt, rdt);
            ulonglong2 o0, o1;
            o0.x = mul2(acc[t][0], r2); o0.y = mul2(acc[t][1], r2);
            o1.x = mul2(acc[t][2], r2); o1.y = mul2(acc[t][3], r2);
            ulonglong2* op = (ulonglong2*)(out + base + row * DIM + doff);
            op[0] = o0; op[1] = o1;
        }
    }
}

extern "C" void kernel_launch(void* const* d_in, const int* in_sizes, int n_in,
                              void* d_out, int out_size) {
    const float* q = (const float*)d_in[0];
    const float* k = (const float*)d_in[1];
    const float* v = (const float*)d_in[2];
    float* out = (float*)d_out;

    int n = in_sizes[0];            // B*H*L*D
    int G = n / (W * DIM);          // number of attention blocks (20480)
    int grid = (G + BLK_PER_CTA - 1) / BLK_PER_CTA;
    robust_attn_kernel<<<grid, NTHREADS>>>(q, k, v, out, G);
}

// round 10
// speedup vs baseline: 1.1507x; 1.1507x over previous
#include <cuda_runtime.h>

#define W 15            // attention block length
#define DIM 64          // head dim
#define BLK_PER_CTA 4   // one block per warp
#define NTHREADS 128
#define EPS 1e-6f

typedef unsigned long long ull;

__device__ __forceinline__ ull pack2(float lo, float hi) {
    ull r; asm("mov.b64 %0, {%1,%2};" : "=l"(r) : "f"(lo), "f"(hi)); return r;
}
__device__ __forceinline__ void unpack2(ull v, float& lo, float& hi) {
    asm("mov.b64 {%0,%1}, %2;" : "=f"(lo), "=f"(hi) : "l"(v));
}
__device__ __forceinline__ ull fma2(ull a, ull b, ull c) {
    ull d; asm("fma.rn.f32x2 %0, %1, %2, %3;" : "=l"(d) : "l"(a), "l"(b), "l"(c)); return d;
}
__device__ __forceinline__ ull mul2(ull a, ull b) {
    ull d; asm("mul.rn.f32x2 %0, %1, %2;" : "=l"(d) : "l"(a), "l"(b)); return d;
}
__device__ __forceinline__ float shxor(float v, int m) {
    return __shfl_xor_sync(0xffffffffu, v, m, 32);
}

// angle-step literals (phi = pi/30)
#define CA1 0.9945218953682733f   // cos(phi)
#define SA1 0.1045284632676535f   // sin(phi)
#define CA4 0.9135454576426009f   // cos(4*phi)
#define SA4 0.4067366430758002f   // sin(4*phi)
#define CG2 0.9781476007338057f   // cos(2*phi)
#define SG2 0.2079116908177593f
#define CG3 0.9510565162951535f   // cos(3*phi)
#define SG3 0.3090169943749474f

__global__ void __launch_bounds__(NTHREADS, 5)
robust_attn_kernel(const float* __restrict__ q, const float* __restrict__ k,
                   const float* __restrict__ v, float* __restrict__ out, int G)
{
    // relu'd K,V; each warp owns a private 960-float region (no barrier needed)
    __shared__ float sK[BLK_PER_CTA * W * DIM];
    __shared__ float sV[BLK_PER_CTA * W * DIM];

    const int tid = threadIdx.x;
    const int warp = tid >> 5;
    const int lane = tid & 31;
    const int blk = blockIdx.x * BLK_PER_CTA + warp;
    if (blk >= G) return;                       // safe: no CTA-wide sync anywhere
    const size_t base = (size_t)blk * (W * DIM);

    // ---- per-warp fill of own block: 16 batched LDG.128, relu at store ----
    {
        const float4* gk = (const float4*)(k + base);
        const float4* gv = (const float4*)(v + base);
        float4 tk[8], tv[8];
        #pragma unroll
        for (int it = 0; it < 8; ++it) {
            int i4 = it * 32 + lane;            // 0..255, valid < 240
            bool ok = (it < 7) || (lane < 16);
            if (ok) { tk[it] = gk[i4]; tv[it] = gv[i4]; }
        }
        float* wK = &sK[warp * (W * DIM)];
        float* wV = &sV[warp * (W * DIM)];
        #pragma unroll
        for (int it = 0; it < 8; ++it) {
            int i4 = it * 32 + lane;
            bool ok = (it < 7) || (lane < 16);
            if (ok) {
                float4 a = tk[it];
                a.x = fmaxf(a.x, 0.f); a.y = fmaxf(a.y, 0.f);
                a.z = fmaxf(a.z, 0.f); a.w = fmaxf(a.w, 0.f);
                *(float4*)&wK[i4 * 4] = a;
                float4 b = tv[it];
                b.x = fmaxf(b.x, 0.f); b.y = fmaxf(b.y, 0.f);
                b.z = fmaxf(b.z, 0.f); b.w = fmaxf(b.w, 0.f);
                *(float4*)&wV[i4 * 4] = b;
            }
        }
    }

    const int g = lane & 3;       // row-group: rows g, g+4, g+8, g+12
    const int d = lane >> 2;      // dim-group: dims {4d..4d+3} U {32+4d..32+4d+3}
    const int c0 = d * 4;         // first 16B chunk (floats)
    const int c1 = 32 + d * 4;    // second 16B chunk (floats)

    // ---- per-lane cos/sin of own row angles ----
    float cg = (g == 0) ? 1.0f : (g == 1) ? CA1 : (g == 2) ? CG2 : CG3;
    float sg = (g == 0) ? 0.0f : (g == 1) ? SA1 : (g == 2) ? SG2 : SG3;
    float ci[4], si[4];
    ci[0] = cg; si[0] = sg;
    #pragma unroll
    for (int t = 1; t < 4; ++t) {
        ci[t] = ci[t-1] * CA4 - si[t-1] * SA4;
        si[t] = si[t-1] * CA4 + ci[t-1] * SA4;
    }

    // ---- load + relu q slices for my 4 rows (two 16B chunks per row) ----
    ull q2[4][4];
    #pragma unroll
    for (int t = 0; t < 4; ++t) {
        int row = g + 4 * t; if (row > W - 1) row = W - 1;
        const float* qr = q + base + row * DIM;
        float4 a = *(const float4*)(qr + c0);
        float4 b = *(const float4*)(qr + c1);
        q2[t][0] = pack2(fmaxf(a.x, 0.f), fmaxf(a.y, 0.f));
        q2[t][1] = pack2(fmaxf(a.z, 0.f), fmaxf(a.w, 0.f));
        q2[t][2] = pack2(fmaxf(b.x, 0.f), fmaxf(b.y, 0.f));
        q2[t][3] = pack2(fmaxf(b.z, 0.f), fmaxf(b.w, 0.f));
    }

    __syncwarp();

    ull acc[4][4];
    #pragma unroll
    for (int t = 0; t < 4; ++t)
        #pragma unroll
        for (int e = 0; e < 4; ++e) acc[t][e] = 0ULL;
    float dn[4] = {0.f, 0.f, 0.f, 0.f};

    const int sbase = warp * (W * DIM);

    // ---- fused pass over j: conflict-free LDS (16B lane stride per instr) ----
    float cj = 1.0f, sj = 0.0f;   // cos/sin(j*phi)
    #pragma unroll
    for (int j = 0; j < W; ++j) {
        const float* kr = &sK[sbase + j * DIM];
        ulonglong2 kA = *(const ulonglong2*)(kr + c0);   // lanes: 0..127B contiguous
        ulonglong2 kB = *(const ulonglong2*)(kr + c1);   // lanes: 128..255B contiguous
        const float* vr = &sV[sbase + j * DIM];
        ulonglong2 vA = *(const ulonglong2*)(vr + c0);
        ulonglong2 vB = *(const ulonglong2*)(vr + c1);

        #pragma unroll
        for (int t = 0; t < 4; ++t) {
            if (4 * t + 3 >= j) {          // compile-time skip of impossible pairs
                ull a = mul2(q2[t][0], kA.x);
                a = fma2(q2[t][1], kA.y, a);
                a = fma2(q2[t][2], kB.x, a);
                a = fma2(q2[t][3], kB.y, a);
                float pl, ph; unpack2(a, pl, ph);
                float pf = pl + ph;
                pf += shxor(pf, 4);
                pf += shxor(pf, 8);
                pf += shxor(pf, 16);
                float s = pf * (ci[t] * cj + si[t] * sj);
                if (4 * t < j) s = (g >= j - 4 * t) ? s : 0.f;
                dn[t] += s;
                ull s2 = pack2(s, s);
                acc[t][0] = fma2(s2, vA.x, acc[t][0]);
                acc[t][1] = fma2(s2, vA.y, acc[t][1]);
                acc[t][2] = fma2(s2, vB.x, acc[t][2]);
                acc[t][3] = fma2(s2, vB.y, acc[t][3]);
            }
        }
        float cjn = cj * CA1 - sj * SA1;
        sj = sj * CA1 + cj * SA1;
        cj = cjn;
    }

    // ---- normalize + store (same two 16B chunks per row) ----
    #pragma unroll
    for (int t = 0; t < 4; ++t) {
        int row = g + 4 * t;
        if (row < W) {
            float rdt = __fdividef(1.0f, fmaxf(dn[t], EPS));
            ull r2 = pack2(rdt, rdt);
            float* op = out + base + row * DIM;
            ulonglong2 o0, o1;
            o0.x = mul2(acc[t][0], r2); o0.y = mul2(acc[t][1], r2);
            o1.x = mul2(acc[t][2], r2); o1.y = mul2(acc[t][3], r2);
            *(ulonglong2*)(op + c0) = o0;
            *(ulonglong2*)(op + c1) = o1;
        }
    }
}

extern "C" void kernel_launch(void* const* d_in, const int* in_sizes, int n_in,
                              void* d_out, int out_size) {
    const float* q = (const float*)d_in[0];
    const float* k = (const float*)d_in[1];
    const float* v = (const float*)d_in[2];
    float* out = (float*)d_out;

    int n = in_sizes[0];            // B*H*L*D
    int G = n / (W * DIM);          // number of attention blocks (20480)
    int grid = (G + BLK_PER_CTA - 1) / BLK_PER_CTA;
    robust_attn_kernel<<<grid, NTHREADS>>>(q, k, v, out, G);
}

// round 11
// speedup vs baseline: 1.2111x; 1.0525x over previous
#include <cuda_runtime.h>
#include <cuda_fp16.h>

#define W 15            // attention block length
#define DIM 64          // head dim
#define BLK_PER_CTA 4   // one block per warp
#define NTHREADS 128
#define EPS 1e-6f

typedef unsigned long long ull;

__device__ __forceinline__ ull pack2(float lo, float hi) {
    ull r; asm("mov.b64 %0, {%1,%2};" : "=l"(r) : "f"(lo), "f"(hi)); return r;
}
__device__ __forceinline__ ull fma2(ull a, ull b, ull c) {
    ull d; asm("fma.rn.f32x2 %0, %1, %2, %3;" : "=l"(d) : "l"(a), "l"(b), "l"(c)); return d;
}
__device__ __forceinline__ ull mul2(ull a, ull b) {
    ull d; asm("mul.rn.f32x2 %0, %1, %2;" : "=l"(d) : "l"(a), "l"(b)); return d;
}
__device__ __forceinline__ float shxor(float v, int m) {
    return __shfl_xor_sync(0xffffffffu, v, m, 32);
}
__device__ __forceinline__ __half2 u2h(unsigned u) {
    __half2 h; *(unsigned*)&h = u; return h;
}

// angle-step literals (phi = pi/30)
#define CA1 0.9945218953682733f   // cos(phi)
#define SA1 0.1045284632676535f   // sin(phi)
#define CA4 0.9135454576426009f   // cos(4*phi)
#define SA4 0.4067366430758002f   // sin(4*phi)
#define CG2 0.9781476007338057f   // cos(2*phi)
#define SG2 0.2079116908177593f
#define CG3 0.9510565162951535f   // cos(3*phi)
#define SG3 0.3090169943749474f

__global__ void __launch_bounds__(NTHREADS, 5)
robust_attn_kernel(const float* __restrict__ q, const float* __restrict__ k,
                   const float* __restrict__ v, float* __restrict__ out, int G)
{
    // K: relu'd fp16, permuted so lane d's 8 dims are contiguous (16B).
    // V: relu'd fp32, gmem layout (as R10).
    __shared__ unsigned short sKh[BLK_PER_CTA * W * DIM];   // 7.5 KB
    __shared__ float sV[BLK_PER_CTA * W * DIM];             // 15 KB

    const int tid = threadIdx.x;
    const int warp = tid >> 5;
    const int lane = tid & 31;
    const int blk = blockIdx.x * BLK_PER_CTA + warp;
    if (blk >= G) return;                       // safe: no CTA-wide sync anywhere
    const size_t base = (size_t)blk * (W * DIM);

    // ---- per-warp fill: 16 batched LDG.128; K -> fp16 permuted, V -> fp32 ----
    {
        const float4* gk = (const float4*)(k + base);
        const float4* gv = (const float4*)(v + base);
        float4 tk[8], tv[8];
        #pragma unroll
        for (int it = 0; it < 8; ++it) {
            int i4 = it * 32 + lane;            // 0..255, valid < 240
            bool ok = (it < 7) || (lane < 16);
            if (ok) { tk[it] = gk[i4]; tv[it] = gv[i4]; }
        }
        unsigned short* wK = &sKh[warp * (W * DIM)];
        float* wV = &sV[warp * (W * DIM)];
        #pragma unroll
        for (int it = 0; it < 8; ++it) {
            int i4 = it * 32 + lane;
            bool ok = (it < 7) || (lane < 16);
            if (ok) {
                int r = i4 >> 4;                // row 0..14
                int c = i4 & 15;                // 16B chunk within row
                float4 a = tk[it];
                __half2 h0 = __floats2half2_rn(fmaxf(a.x, 0.f), fmaxf(a.y, 0.f));
                __half2 h1 = __floats2half2_rn(fmaxf(a.z, 0.f), fmaxf(a.w, 0.f));
                // perm: chunk c<8 -> lane d=c first half; c>=8 -> lane d=c-8 second half
                int hoff = r * 64 + (c & 7) * 8 + (c >> 3) * 4;   // in halfs
                uint2 kp; kp.x = *(unsigned*)&h0; kp.y = *(unsigned*)&h1;
                *(uint2*)&wK[hoff] = kp;
                float4 b = tv[it];
                b.x = fmaxf(b.x, 0.f); b.y = fmaxf(b.y, 0.f);
                b.z = fmaxf(b.z, 0.f); b.w = fmaxf(b.w, 0.f);
                *(float4*)&wV[i4 * 4] = b;
            }
        }
    }

    const int g = lane & 3;       // row-group: rows g, g+4, g+8, g+12
    const int d = lane >> 2;      // dim-group: dims {4d..4d+3} U {32+4d..32+4d+3}
    const int c0 = d * 4;         // first 16B chunk of V (floats)
    const int c1 = 32 + d * 4;    // second 16B chunk of V (floats)

    // ---- per-lane cos/sin of own row angles ----
    float cg = (g == 0) ? 1.0f : (g == 1) ? CA1 : (g == 2) ? CG2 : CG3;
    float sg = (g == 0) ? 0.0f : (g == 1) ? SA1 : (g == 2) ? SG2 : SG3;
    float ci[4], si[4];
    ci[0] = cg; si[0] = sg;
    #pragma unroll
    for (int t = 1; t < 4; ++t) {
        ci[t] = ci[t-1] * CA4 - si[t-1] * SA4;
        si[t] = si[t-1] * CA4 + ci[t-1] * SA4;
    }

    // ---- load + relu q, convert to fp16x2 (pairing matches K perm layout) ----
    __half2 q2h[4][4];
    #pragma unroll
    for (int t = 0; t < 4; ++t) {
        int row = g + 4 * t; if (row > W - 1) row = W - 1;
        const float* qr = q + base + row * DIM;
        float4 a = *(const float4*)(qr + c0);
        float4 b = *(const float4*)(qr + c1);
        q2h[t][0] = __floats2half2_rn(fmaxf(a.x, 0.f), fmaxf(a.y, 0.f));
        q2h[t][1] = __floats2half2_rn(fmaxf(a.z, 0.f), fmaxf(a.w, 0.f));
        q2h[t][2] = __floats2half2_rn(fmaxf(b.x, 0.f), fmaxf(b.y, 0.f));
        q2h[t][3] = __floats2half2_rn(fmaxf(b.z, 0.f), fmaxf(b.w, 0.f));
    }

    __syncwarp();

    ull acc[4][4];
    #pragma unroll
    for (int t = 0; t < 4; ++t)
        #pragma unroll
        for (int e = 0; e < 4; ++e) acc[t][e] = 0ULL;
    float dn[4] = {0.f, 0.f, 0.f, 0.f};

    const int skbase = warp * (W * DIM);
    const int svbase = warp * (W * DIM);

    // ---- fused pass over j: 1 fp16 K LDS + 2 fp32 V LDS per lane per j ----
    float cj = 1.0f, sj = 0.0f;   // cos/sin(j*phi)
    #pragma unroll
    for (int j = 0; j < W; ++j) {
        uint4 kw = *(const uint4*)&sKh[skbase + j * DIM + d * 8];  // 8 fp16 dims
        const float* vr = &sV[svbase + j * DIM];
        ulonglong2 vA = *(const ulonglong2*)(vr + c0);
        ulonglong2 vB = *(const ulonglong2*)(vr + c1);

        #pragma unroll
        for (int t = 0; t < 4; ++t) {
            if (4 * t + 3 >= j) {          // compile-time skip of impossible pairs
                // two independent half2 dot chains
                __half2 p0 = __hmul2(q2h[t][0], u2h(kw.x));
                __half2 p1 = __hmul2(q2h[t][1], u2h(kw.y));
                p0 = __hfma2(q2h[t][2], u2h(kw.z), p0);
                p1 = __hfma2(q2h[t][3], u2h(kw.w), p1);
                float2 f0 = __half22float2(p0);
                float2 f1 = __half22float2(p1);
                float pf = (f0.x + f0.y) + (f1.x + f1.y);
                pf += shxor(pf, 4);
                pf += shxor(pf, 8);
                pf += shxor(pf, 16);
                float s = pf * (ci[t] * cj + si[t] * sj);
                if (4 * t < j) s = (g >= j - 4 * t) ? s : 0.f;
                dn[t] += s;
                ull s2 = pack2(s, s);
                acc[t][0] = fma2(s2, vA.x, acc[t][0]);
                acc[t][1] = fma2(s2, vA.y, acc[t][1]);
                acc[t][2] = fma2(s2, vB.x, acc[t][2]);
                acc[t][3] = fma2(s2, vB.y, acc[t][3]);
            }
        }
        float cjn = cj * CA1 - sj * SA1;
        sj = sj * CA1 + cj * SA1;
        cj = cjn;
    }

    // ---- normalize + store ----
    #pragma unroll
    for (int t = 0; t < 4; ++t) {
        int row = g + 4 * t;
        if (row < W) {
            float rdt = __fdividef(1.0f, fmaxf(dn[t], EPS));
            ull r2 = pack2(rdt, rdt);
            float* op = out + base + row * DIM;
            ulonglong2 o0, o1;
            o0.x = mul2(acc[t][0], r2); o0.y = mul2(acc[t][1], r2);
            o1.x = mul2(acc[t][2], r2); o1.y = mul2(acc[t][3], r2);
            *(ulonglong2*)(op + c0) = o0;
            *(ulonglong2*)(op + c1) = o1;
        }
    }
}

extern "C" void kernel_launch(void* const* d_in, const int* in_sizes, int n_in,
                              void* d_out, int out_size) {
    const float* q = (const float*)d_in[0];
    const float* k = (const float*)d_in[1];
    const float* v = (const float*)d_in[2];
    float* out = (float*)d_out;

    int n = in_sizes[0];            // B*H*L*D
    int G = n / (W * DIM);          // number of attention blocks (20480)
    int grid = (G + BLK_PER_CTA - 1) / BLK_PER_CTA;
    robust_attn_kernel<<<grid, NTHREADS>>>(q, k, v, out, G);
}

// round 12
// speedup vs baseline: 1.2226x; 1.0095x over previous
#include <cuda_runtime.h>
#include <cuda_fp16.h>

#define W 15            // attention block length
#define DIM 64          // head dim
#define BLK_PER_CTA 4   // one block per warp
#define NTHREADS 128
#define EPS 1e-6f

typedef unsigned long long ull;

__device__ __forceinline__ ull pack2(float lo, float hi) {
    ull r; asm("mov.b64 %0, {%1,%2};" : "=l"(r) : "f"(lo), "f"(hi)); return r;
}
__device__ __forceinline__ ull fma2(ull a, ull b, ull c) {
    ull d; asm("fma.rn.f32x2 %0, %1, %2, %3;" : "=l"(d) : "l"(a), "l"(b), "l"(c)); return d;
}
__device__ __forceinline__ ull mul2(ull a, ull b) {
    ull d; asm("mul.rn.f32x2 %0, %1, %2;" : "=l"(d) : "l"(a), "l"(b)); return d;
}
__device__ __forceinline__ float shxor(float v, int m) {
    return __shfl_xor_sync(0xffffffffu, v, m, 32);
}
__device__ __forceinline__ __half2 u2h(unsigned u) {
    __half2 h; *(unsigned*)&h = u; return h;
}
__device__ __forceinline__ ull h2_to_f32x2(unsigned u) {
    float2 f = __half22float2(u2h(u));
    return pack2(f.x, f.y);
}

// angle-step literals (phi = pi/30)
#define CA1 0.9945218953682733f   // cos(phi)
#define SA1 0.1045284632676535f   // sin(phi)
#define CA4 0.9135454576426009f   // cos(4*phi)
#define SA4 0.4067366430758002f   // sin(4*phi)
#define CG2 0.9781476007338057f   // cos(2*phi)
#define SG2 0.2079116908177593f
#define CG3 0.9510565162951535f   // cos(3*phi)
#define SG3 0.3090169943749474f

__global__ void __launch_bounds__(NTHREADS, 5)
robust_attn_kernel(const float* __restrict__ q, const float* __restrict__ k,
                   const float* __restrict__ v, float* __restrict__ out, int G)
{
    // K,V: relu'd fp16, permuted so lane d's 8 dims are contiguous (16B).
    __shared__ unsigned short sKh[BLK_PER_CTA * W * DIM];   // 7.5 KB
    __shared__ unsigned short sVh[BLK_PER_CTA * W * DIM];   // 7.5 KB

    const int tid = threadIdx.x;
    const int warp = tid >> 5;
    const int lane = tid & 31;
    const int blk = blockIdx.x * BLK_PER_CTA + warp;
    if (blk >= G) return;                       // safe: no CTA-wide sync anywhere
    const size_t base = (size_t)blk * (W * DIM);

    // ---- per-warp fill: 16 batched LDG.128; K,V -> fp16 permuted ----
    {
        const float4* gk = (const float4*)(k + base);
        const float4* gv = (const float4*)(v + base);
        float4 tk[8], tv[8];
        #pragma unroll
        for (int it = 0; it < 8; ++it) {
            int i4 = it * 32 + lane;            // 0..255, valid < 240
            bool ok = (it < 7) || (lane < 16);
            if (ok) { tk[it] = gk[i4]; tv[it] = gv[i4]; }
        }
        unsigned short* wK = &sKh[warp * (W * DIM)];
        unsigned short* wV = &sVh[warp * (W * DIM)];
        #pragma unroll
        for (int it = 0; it < 8; ++it) {
            int i4 = it * 32 + lane;
            bool ok = (it < 7) || (lane < 16);
            if (ok) {
                int r = i4 >> 4;                // row 0..14
                int c = i4 & 15;                // 16B chunk within row
                // perm: chunk c<8 -> lane d=c first half; c>=8 -> lane d=c-8 second half
                int hoff = r * 64 + (c & 7) * 8 + (c >> 3) * 4;   // in halfs
                float4 a = tk[it];
                __half2 h0 = __floats2half2_rn(fmaxf(a.x, 0.f), fmaxf(a.y, 0.f));
                __half2 h1 = __floats2half2_rn(fmaxf(a.z, 0.f), fmaxf(a.w, 0.f));
                uint2 kp; kp.x = *(unsigned*)&h0; kp.y = *(unsigned*)&h1;
                *(uint2*)&wK[hoff] = kp;
                float4 b = tv[it];
                __half2 g0 = __floats2half2_rn(fmaxf(b.x, 0.f), fmaxf(b.y, 0.f));
                __half2 g1 = __floats2half2_rn(fmaxf(b.z, 0.f), fmaxf(b.w, 0.f));
                uint2 vp; vp.x = *(unsigned*)&g0; vp.y = *(unsigned*)&g1;
                *(uint2*)&wV[hoff] = vp;
            }
        }
    }

    const int g = lane & 3;       // row-group: rows g, g+4, g+8, g+12
    const int d = lane >> 2;      // dim-group: dims {4d..4d+3} U {32+4d..32+4d+3}
    const int c0 = d * 4;         // first 16B chunk (floats, gmem layout)
    const int c1 = 32 + d * 4;    // second 16B chunk (floats, gmem layout)

    // ---- per-lane cos/sin of own row angles ----
    float cg = (g == 0) ? 1.0f : (g == 1) ? CA1 : (g == 2) ? CG2 : CG3;
    float sg = (g == 0) ? 0.0f : (g == 1) ? SA1 : (g == 2) ? SG2 : SG3;
    float ci[4], si[4];
    ci[0] = cg; si[0] = sg;
    #pragma unroll
    for (int t = 1; t < 4; ++t) {
        ci[t] = ci[t-1] * CA4 - si[t-1] * SA4;
        si[t] = si[t-1] * CA4 + ci[t-1] * SA4;
    }

    // ---- load + relu q, convert to fp16x2 (pairing matches K perm layout) ----
    __half2 q2h[4][4];
    #pragma unroll
    for (int t = 0; t < 4; ++t) {
        int row = g + 4 * t; if (row > W - 1) row = W - 1;
        const float* qr = q + base + row * DIM;
        float4 a = *(const float4*)(qr + c0);
        float4 b = *(const float4*)(qr + c1);
        q2h[t][0] = __floats2half2_rn(fmaxf(a.x, 0.f), fmaxf(a.y, 0.f));
        q2h[t][1] = __floats2half2_rn(fmaxf(a.z, 0.f), fmaxf(a.w, 0.f));
        q2h[t][2] = __floats2half2_rn(fmaxf(b.x, 0.f), fmaxf(b.y, 0.f));
        q2h[t][3] = __floats2half2_rn(fmaxf(b.z, 0.f), fmaxf(b.w, 0.f));
    }

    __syncwarp();

    ull acc[4][4];
    #pragma unroll
    for (int t = 0; t < 4; ++t)
        #pragma unroll
        for (int e = 0; e < 4; ++e) acc[t][e] = 0ULL;
    float dn[4] = {0.f, 0.f, 0.f, 0.f};

    const int sbase = warp * (W * DIM);

    // ---- fused pass over j: 1 fp16 K LDS + 1 fp16 V LDS per lane per j ----
    float cj = 1.0f, sj = 0.0f;   // cos/sin(j*phi)
    #pragma unroll
    for (int j = 0; j < W; ++j) {
        uint4 kw = *(const uint4*)&sKh[sbase + j * DIM + d * 8];  // 8 fp16 dims
        uint4 vw = *(const uint4*)&sVh[sbase + j * DIM + d * 8];

        // convert V once per j to packed f32x2 (shared across all active t)
        ull va = h2_to_f32x2(vw.x);
        ull vb = h2_to_f32x2(vw.y);
        ull vc = h2_to_f32x2(vw.z);
        ull vd = h2_to_f32x2(vw.w);

        #pragma unroll
        for (int t = 0; t < 4; ++t) {
            if (4 * t + 3 >= j) {          // compile-time skip of impossible pairs
                // two independent half2 dot chains
                __half2 p0 = __hmul2(q2h[t][0], u2h(kw.x));
                __half2 p1 = __hmul2(q2h[t][1], u2h(kw.y));
                p0 = __hfma2(q2h[t][2], u2h(kw.z), p0);
                p1 = __hfma2(q2h[t][3], u2h(kw.w), p1);
                float2 f0 = __half22float2(p0);
                float2 f1 = __half22float2(p1);
                float pf = (f0.x + f0.y) + (f1.x + f1.y);
                pf += shxor(pf, 4);
                pf += shxor(pf, 8);
                pf += shxor(pf, 16);
                float s = pf * (ci[t] * cj + si[t] * sj);
                if (4 * t < j) s = (g >= j - 4 * t) ? s : 0.f;
                dn[t] += s;
                ull s2 = pack2(s, s);
                acc[t][0] = fma2(s2, va, acc[t][0]);
                acc[t][1] = fma2(s2, vb, acc[t][1]);
                acc[t][2] = fma2(s2, vc, acc[t][2]);
                acc[t][3] = fma2(s2, vd, acc[t][3]);
            }
        }
        float cjn = cj * CA1 - sj * SA1;
        sj = sj * CA1 + cj * SA1;
        cj = cjn;
    }

    // ---- normalize + store ----
    #pragma unroll
    for (int t = 0; t < 4; ++t) {
        int row = g + 4 * t;
        if (row < W) {
            float rdt = __fdividef(1.0f, fmaxf(dn[t], EPS));
            ull r2 = pack2(rdt, rdt);
            float* op = out + base + row * DIM;
            ulonglong2 o0, o1;
            o0.x = mul2(acc[t][0], r2); o0.y = mul2(acc[t][1], r2);
            o1.x = mul2(acc[t][2], r2); o1.y = mul2(acc[t][3], r2);
            *(ulonglong2*)(op + c0) = o0;
            *(ulonglong2*)(op + c1) = o1;
        }
    }
}

extern "C" void kernel_launch(void* const* d_in, const int* in_sizes, int n_in,
                              void* d_out, int out_size) {
    const float* q = (const float*)d_in[0];
    const float* k = (const float*)d_in[1];
    const float* v = (const float*)d_in[2];
    float* out = (float*)d_out;

    int n = in_sizes[0];            // B*H*L*D
    int G = n / (W * DIM);          // number of attention blocks (20480)
    int grid = (G + BLK_PER_CTA - 1) / BLK_PER_CTA;
    robust_attn_kernel<<<grid, NTHREADS>>>(q, k, v, out, G);
}

// round 13
// speedup vs baseline: 1.2718x; 1.0402x over previous
#include <cuda_runtime.h>
#include <cuda_fp16.h>

#define W 15
#define DIM 64
#define BLK_PER_CTA 4
#define NTHREADS 128
#define EPS 1e-6f
#define PHI 0.10471975511965977f   // pi/30

typedef unsigned int u32;

__device__ __forceinline__ float shxor(float v, int m) {
    return __shfl_xor_sync(0xffffffffu, v, m, 32);
}
__device__ __forceinline__ u32 smem_u32(const void* p) {
    return (u32)__cvta_generic_to_shared(p);
}
__device__ __forceinline__ void ldsm4(u32& r0, u32& r1, u32& r2, u32& r3, u32 a) {
    asm volatile("ldmatrix.sync.aligned.m8n8.x4.shared.b16 {%0,%1,%2,%3}, [%4];"
        : "=r"(r0), "=r"(r1), "=r"(r2), "=r"(r3) : "r"(a));
}
__device__ __forceinline__ void ldsm4t(u32& r0, u32& r1, u32& r2, u32& r3, u32 a) {
    asm volatile("ldmatrix.sync.aligned.m8n8.x4.trans.shared.b16 {%0,%1,%2,%3}, [%4];"
        : "=r"(r0), "=r"(r1), "=r"(r2), "=r"(r3) : "r"(a));
}
__device__ __forceinline__ void mma16816(float* d, const u32* a, u32 b0, u32 b1,
                                         float c0, float c1, float c2, float c3) {
    asm volatile(
        "mma.sync.aligned.m16n8k16.row.col.f32.f16.f16.f32 "
        "{%0,%1,%2,%3},{%4,%5,%6,%7},{%8,%9},{%10,%11,%12,%13};"
        : "=f"(d[0]), "=f"(d[1]), "=f"(d[2]), "=f"(d[3])
        : "r"(a[0]), "r"(a[1]), "r"(a[2]), "r"(a[3]), "r"(b0), "r"(b1),
          "f"(c0), "f"(c1), "f"(c2), "f"(c3));
}
__device__ __forceinline__ u32 h2u(__half2 h) { return *(u32*)&h; }

__global__ void __launch_bounds__(NTHREADS, 6)
robust_attn_kernel(const float* __restrict__ q, const float* __restrict__ k,
                   const float* __restrict__ v, float* __restrict__ out, int G)
{
    // per-warp fp16 tiles, 16 rows x 64 halfs (row 15 zeroed), XOR-swizzled
    __shared__ __align__(16) unsigned short sQ[BLK_PER_CTA][1024];
    __shared__ __align__(16) unsigned short sK[BLK_PER_CTA][1024];
    __shared__ __align__(16) unsigned short sV[BLK_PER_CTA][1024];

    const int tid = threadIdx.x;
    const int warp = tid >> 5;
    const int lane = tid & 31;
    const int blk = blockIdx.x * BLK_PER_CTA + warp;
    if (blk >= G) return;
    const size_t base = (size_t)blk * (W * DIM);

    unsigned short* wQ = sQ[warp];
    unsigned short* wK = sK[warp];
    unsigned short* wV = sV[warp];

    // ---- zero pad row 15 (covers full 128B; swizzle irrelevant for zeros) ----
    if (lane < 16) {
        uint2 z = make_uint2(0u, 0u);
        *(uint2*)&wQ[15 * 64 + lane * 4] = z;
        *(uint2*)&wK[15 * 64 + lane * 4] = z;
        *(uint2*)&wV[15 * 64 + lane * 4] = z;
    }

    // ---- fill: relu + fp32->fp16, swizzled chunk layout ----
    {
        const float4* gq = (const float4*)(q + base);
        const float4* gk = (const float4*)(k + base);
        const float4* gv = (const float4*)(v + base);
        // batch A: Q + K (MLP 16)
        float4 tq[8], tk[8];
        #pragma unroll
        for (int it = 0; it < 8; ++it) {
            int i4 = it * 32 + lane;
            bool ok = (it < 7) || (lane < 16);
            if (ok) { tq[it] = gq[i4]; tk[it] = gk[i4]; }
        }
        #pragma unroll
        for (int it = 0; it < 8; ++it) {
            int i4 = it * 32 + lane;
            bool ok = (it < 7) || (lane < 16);
            if (ok) {
                int r = i4 >> 4, cc = i4 & 15;
                int off = r * 64 + (((cc >> 1) ^ (r & 7)) << 3) + ((cc & 1) << 2);
                float4 a = tq[it];
                uint2 pa;
                pa.x = h2u(__floats2half2_rn(fmaxf(a.x, 0.f), fmaxf(a.y, 0.f)));
                pa.y = h2u(__floats2half2_rn(fmaxf(a.z, 0.f), fmaxf(a.w, 0.f)));
                *(uint2*)&wQ[off] = pa;
                float4 b = tk[it];
                uint2 pb;
                pb.x = h2u(__floats2half2_rn(fmaxf(b.x, 0.f), fmaxf(b.y, 0.f)));
                pb.y = h2u(__floats2half2_rn(fmaxf(b.z, 0.f), fmaxf(b.w, 0.f)));
                *(uint2*)&wK[off] = pb;
            }
        }
        // batch B: V (MLP 8)
        float4 tv[8];
        #pragma unroll
        for (int it = 0; it < 8; ++it) {
            int i4 = it * 32 + lane;
            bool ok = (it < 7) || (lane < 16);
            if (ok) tv[it] = gv[i4];
        }
        #pragma unroll
        for (int it = 0; it < 8; ++it) {
            int i4 = it * 32 + lane;
            bool ok = (it < 7) || (lane < 16);
            if (ok) {
                int r = i4 >> 4, cc = i4 & 15;
                int off = r * 64 + (((cc >> 1) ^ (r & 7)) << 3) + ((cc & 1) << 2);
                float4 c = tv[it];
                uint2 pc;
                pc.x = h2u(__floats2half2_rn(fmaxf(c.x, 0.f), fmaxf(c.y, 0.f)));
                pc.y = h2u(__floats2half2_rn(fmaxf(c.z, 0.f), fmaxf(c.w, 0.f)));
                *(uint2*)&wV[off] = pc;
            }
        }
    }

    // ---- per-lane reweight constants: coef[rh][jj] for (i = l>>2 + 8rh,
    //      j = 2*(l%4) + (jj&1) + 8*(jj>>1)); zero encodes causality & j=15 pad ----
    const int r0 = lane >> 2;
    const int jb = (lane & 3) * 2;
    float coef[2][4];
    #pragma unroll
    for (int rh = 0; rh < 2; ++rh) {
        int i = r0 + rh * 8;
        #pragma unroll
        for (int jj = 0; jj < 4; ++jj) {
            int j = jb + (jj & 1) + (jj >> 1) * 8;
            int dlt = i - j;
            coef[rh][jj] = (dlt >= 0 && j < W) ? cosf((float)dlt * PHI) : 0.f;
        }
    }

    __syncwarp();

    const u32 qb = smem_u32(wQ), kb = smem_u32(wK), vb = smem_u32(wV);

    // ---- load Q (A) and K (B) fragments ----
    u32 aq[4][4], bk[4][4];
    #pragma unroll
    for (int kc = 0; kc < 4; ++kc) {
        {   // A: lanes 0-15 rows 0-15 chunk 2kc; lanes 16-31 rows 0-15 chunk 2kc+1
            int row = lane & 15;
            int ch = 2 * kc + (lane >> 4);
            u32 ad = qb + row * 128 + ((ch ^ (row & 7)) << 4);
            ldsm4(aq[kc][0], aq[kc][1], aq[kc][2], aq[kc][3], ad);
        }
        {   // B(K): lanes 0-7 r0-7 lo, 8-15 r0-7 hi, 16-23 r8-15 lo, 24-31 r8-15 hi
            int row = ((lane >> 4) << 3) + (lane & 7);
            int ch = 2 * kc + ((lane >> 3) & 1);
            u32 ad = kb + row * 128 + ((ch ^ (row & 7)) << 4);
            ldsm4(bk[kc][0], bk[kc][1], bk[kc][2], bk[kc][3], ad);
        }
    }

    // ---- scores: S(16x16) = Q K^T, two n8 tiles, f32 accum ----
    float S0[4] = {0.f, 0.f, 0.f, 0.f};   // j tile 0 (cols 0-7)
    float S1[4] = {0.f, 0.f, 0.f, 0.f};   // j tile 1 (cols 8-15)
    #pragma unroll
    for (int kc = 0; kc < 4; ++kc) {
        mma16816(S0, aq[kc], bk[kc][0], bk[kc][1], S0[0], S0[1], S0[2], S0[3]);
        mma16816(S1, aq[kc], bk[kc][2], bk[kc][3], S1[0], S1[1], S1[2], S1[3]);
    }

    // ---- reweight + causal mask (constants), cvt to fp16 A-fragment ----
    __half2 ah0 = __floats2half2_rn(S0[0] * coef[0][0], S0[1] * coef[0][1]); // row r0,  k=jb,jb+1
    __half2 ah1 = __floats2half2_rn(S0[2] * coef[1][0], S0[3] * coef[1][1]); // row r0+8
    __half2 ah2 = __floats2half2_rn(S1[0] * coef[0][2], S1[1] * coef[0][3]); // row r0,  k+8
    __half2 ah3 = __floats2half2_rn(S1[2] * coef[1][2], S1[3] * coef[1][3]); // row r0+8
    u32 sa[4] = { h2u(ah0), h2u(ah1), h2u(ah2), h2u(ah3) };

    // ---- denominators from the rounded weights (consistent with numerator) ----
    float2 f0 = __half22float2(ah0), f2 = __half22float2(ah2);
    float2 f1 = __half22float2(ah1), f3 = __half22float2(ah3);
    float dn0 = (f0.x + f0.y) + (f2.x + f2.y);
    float dn1 = (f1.x + f1.y) + (f3.x + f3.y);
    dn0 += shxor(dn0, 1); dn0 += shxor(dn0, 2);
    dn1 += shxor(dn1, 1); dn1 += shxor(dn1, 2);
    float rd0 = __fdividef(1.f, fmaxf(dn0, EPS));
    float rd1 = __fdividef(1.f, fmaxf(dn1, EPS));

    // ---- V fragments (trans): pairs p -> n-tiles 2p, 2p+1 ----
    u32 bv[8][2];
    #pragma unroll
    for (int p = 0; p < 4; ++p) {
        int row = lane & 15;
        int ch = 2 * p + (lane >> 4);
        u32 ad = vb + row * 128 + ((ch ^ (row & 7)) << 4);
        u32 t0, t1, t2, t3;
        ldsm4t(t0, t1, t2, t3, ad);
        bv[2 * p][0] = t0; bv[2 * p][1] = t1;
        bv[2 * p + 1][0] = t2; bv[2 * p + 1][1] = t3;
    }

    // ---- O = S' V : 8 n-tiles, then normalize + store ----
    float* ob = out + base;
    #pragma unroll
    for (int nt = 0; nt < 8; ++nt) {
        float O[4];
        mma16816(O, sa, bv[nt][0], bv[nt][1], 0.f, 0.f, 0.f, 0.f);
        int col = nt * 8 + jb;
        float2 lo; lo.x = O[0] * rd0; lo.y = O[1] * rd0;
        *(float2*)&ob[r0 * 64 + col] = lo;
        if (r0 != 7) {   // row r0+8 == 15 is padding
            float2 hi; hi.x = O[2] * rd1; hi.y = O[3] * rd1;
            *(float2*)&ob[(r0 + 8) * 64 + col] = hi;
        }
    }
}

extern "C" void kernel_launch(void* const* d_in, const int* in_sizes, int n_in,
                              void* d_out, int out_size) {
    const float* q = (const float*)d_in[0];
    const float* k = (const float*)d_in[1];
    const float* v = (const float*)d_in[2];
    float* out = (float*)d_out;

    int n = in_sizes[0];            // B*H*L*D
    int G = n / (W * DIM);          // number of attention blocks (20480)
    int grid = (G + BLK_PER_CTA - 1) / BLK_PER_CTA;
    robust_attn_kernel<<<grid, NTHREADS>>>(q, k, v, out, G);
}